// round 4
// baseline (speedup 1.0000x reference)
#include <cuda_runtime.h>
#include <cuda_fp16.h>

#define FN   262144
#define FNC  4096
#define FD   5
#define FK   4
#define W_JAC (2.0f/3.0f)

// ---- static device scratch -------------------------------------------------
__device__ float  g_Ac[FNC * FNC];     // fp32 RAP accumulator (re-zeroed each call)
__device__ __half g_Ach[FNC * FNC];    // fp16 coarse operator for matvecs
__device__ float  g_wdc[FNC];          // W / diag(Ac)
__device__ float  g_bc[FNC];
__device__ float  g_xc[2 * FNC];
__device__ float  g_xbuf[2 * FN];
// transposed (SoA) fine-grid data
__device__ float  g_diag[FN];
__device__ float  g_winv[FN];          // W / diag
__device__ float  g_offv[4][FN];
__device__ int    g_offc[4][FN];
__device__ float  g_pv[4][FN];
__device__ int    g_pc[4][FN];

// ---- prep: AoS -> SoA ------------------------------------------------------
__global__ void k_prep(const float* __restrict__ Av, const int* __restrict__ Acl,
                       const float* __restrict__ Pv, const int* __restrict__ Pc) {
    int i = blockIdx.x * blockDim.x + threadIdx.x;
    if (i >= FN) return;
    float d = __ldg(&Av[i * FD]);
    g_diag[i] = d;
    g_winv[i] = W_JAC / d;
#pragma unroll
    for (int j = 0; j < 4; j++) {
        g_offv[j][i] = __ldg(&Av[i * FD + 1 + j]);
        g_offc[j][i] = __ldg(&Acl[i * FD + 1 + j]);
    }
    float4 pv = __ldg((const float4*)(Pv + i * 4));
    int4   pc = __ldg((const int4*)(Pc + i * 4));
    g_pv[0][i] = pv.x; g_pv[1][i] = pv.y; g_pv[2][i] = pv.z; g_pv[3][i] = pv.w;
    g_pc[0][i] = pc.x; g_pc[1][i] = pc.y; g_pc[2][i] = pc.z; g_pc[3][i] = pc.w;
}

// ---- RAP: one thread per (row, nz); 16 atomics each ------------------------
__global__ void k_rap(const float* __restrict__ Av, const int* __restrict__ Acl,
                      const float* __restrict__ Pv, const int* __restrict__ Pc) {
    int t = blockIdx.x * blockDim.x + threadIdx.x;
    if (t >= FN * FD) return;
    int i = t / FD;
    int j = t - i * FD;
    int cj = __ldg(&Acl[i * FD + j]);
    float a = __ldg(&Av[i * FD + j]);
    float4 pa4 = __ldg((const float4*)(Pv + i * 4));
    int4   ia4 = __ldg((const int4*)(Pc + i * 4));
    float4 qb4 = __ldg((const float4*)(Pv + cj * 4));
    int4   ib4 = __ldg((const int4*)(Pc + cj * 4));
    float pa[FK] = {pa4.x * a, pa4.y * a, pa4.z * a, pa4.w * a};
    int   ia[FK] = {ia4.x, ia4.y, ia4.z, ia4.w};
    float qb[FK] = {qb4.x, qb4.y, qb4.z, qb4.w};
    int   ib[FK] = {ib4.x, ib4.y, ib4.z, ib4.w};
#pragma unroll
    for (int ka = 0; ka < FK; ka++) {
        int base = ia[ka] * FNC;
#pragma unroll
        for (int kb = 0; kb < FK; kb++)
            atomicAdd(&g_Ac[base + ib[kb]], pa[ka] * qb[kb]);
    }
}

// ---- convert fp32 Ac -> fp16, extract W/diag, re-zero fp32 Ac --------------
__global__ void k_convert() {
    size_t base = (size_t)(blockIdx.x * blockDim.x + threadIdx.x) * 8;
    float4 a = *(const float4*)(g_Ac + base);
    float4 b = *(const float4*)(g_Ac + base + 4);
    __half2* h = (__half2*)(g_Ach + base);
    h[0] = __floats2half2_rn(a.x, a.y);
    h[1] = __floats2half2_rn(a.z, a.w);
    h[2] = __floats2half2_rn(b.x, b.y);
    h[3] = __floats2half2_rn(b.z, b.w);
    int r = (int)(base >> 12);
    size_t dpos = ((size_t)r << 12) + r;
    if (dpos >= base && dpos < base + 8) {
        int o = (int)(dpos - base);
        float dv = (o == 0) ? a.x : (o == 1) ? a.y : (o == 2) ? a.z : (o == 3) ? a.w
                 : (o == 4) ? b.x : (o == 5) ? b.y : (o == 6) ? b.z : b.w;
        g_wdc[r] = W_JAC / dv;
    }
    float4 z = make_float4(0.f, 0.f, 0.f, 0.f);
    *(float4*)(g_Ac + base) = z;
    *(float4*)(g_Ac + base + 4) = z;
}

// ---- fine smoother: 4 rows/thread, SoA, xout = (1-W)x + winv*(b - offsum) --
__global__ void k_smooth(const float* __restrict__ xin, float* __restrict__ xout,
                         const float* __restrict__ b) {
    int t = blockIdx.x * blockDim.x + threadIdx.x;   // t < FN/4
    float4 xi = __ldg((const float4*)xin + t);
    float4 bi = __ldg((const float4*)b + t);
    float4 wv = *((const float4*)g_winv + t);
    float4 s = bi;
#pragma unroll
    for (int j = 0; j < 4; j++) {
        float4 v = *((const float4*)g_offv[j] + t);
        int4   c = *((const int4*)g_offc[j] + t);
        s.x -= v.x * __ldg(&xin[c.x]);
        s.y -= v.y * __ldg(&xin[c.y]);
        s.z -= v.z * __ldg(&xin[c.z]);
        s.w -= v.w * __ldg(&xin[c.w]);
    }
    float4 o;
    const float omw = 1.f - W_JAC;
    o.x = omw * xi.x + wv.x * s.x;
    o.y = omw * xi.y + wv.y * s.y;
    o.z = omw * xi.z + wv.z * s.z;
    o.w = omw * xi.w + wv.w * s.w;
    ((float4*)xout)[t] = o;
}

// ---- residual + restriction: bc += P^T (b - A x) ---------------------------
__global__ void k_resid_bc(const float* __restrict__ xin, const float* __restrict__ b) {
    int t = blockIdx.x * blockDim.x + threadIdx.x;   // t < FN/4
    float4 xi = __ldg((const float4*)xin + t);
    float4 bi = __ldg((const float4*)b + t);
    float4 dg = *((const float4*)g_diag + t);
    float4 r;
    r.x = bi.x - dg.x * xi.x;
    r.y = bi.y - dg.y * xi.y;
    r.z = bi.z - dg.z * xi.z;
    r.w = bi.w - dg.w * xi.w;
#pragma unroll
    for (int j = 0; j < 4; j++) {
        float4 v = *((const float4*)g_offv[j] + t);
        int4   c = *((const int4*)g_offc[j] + t);
        r.x -= v.x * __ldg(&xin[c.x]);
        r.y -= v.y * __ldg(&xin[c.y]);
        r.z -= v.z * __ldg(&xin[c.z]);
        r.w -= v.w * __ldg(&xin[c.w]);
    }
#pragma unroll
    for (int k = 0; k < 4; k++) {
        float4 pv = *((const float4*)g_pv[k] + t);
        int4   pc = *((const int4*)g_pc[k] + t);
        atomicAdd(&g_bc[pc.x], pv.x * r.x);
        atomicAdd(&g_bc[pc.y], pv.y * r.y);
        atomicAdd(&g_bc[pc.z], pv.z * r.z);
        atomicAdd(&g_bc[pc.w], pv.w * r.w);
    }
}

__global__ void k_zero_bc() {
    int c = blockIdx.x * blockDim.x + threadIdx.x;
    if (c < FNC) g_bc[c] = 0.f;
}

__global__ void k_cfirst(float* __restrict__ xc) {
    int c = blockIdx.x * blockDim.x + threadIdx.x;
    if (c < FNC) xc[c] = g_bc[c] * g_wdc[c];
}

// ---- coarse Jacobi sweep: fp16 dense matvec, warp per row ------------------
__global__ void k_citer(const float* __restrict__ xin, float* __restrict__ xout) {
    int gw = (blockIdx.x * blockDim.x + threadIdx.x) >> 5;
    int lane = threadIdx.x & 31;
    const uint4* row = (const uint4*)(g_Ach + (size_t)gw * FNC);
    const float4* xv = (const float4*)xin;
    float s = 0.f;
#pragma unroll 4
    for (int it = 0; it < 16; it++) {
        int idx = it * 32 + lane;
        uint4 a = row[idx];
        float4 x0 = __ldg(xv + idx * 2);
        float4 x1 = __ldg(xv + idx * 2 + 1);
        float2 f;
        f = __half22float2(*(__half2*)&a.x); s += f.x * x0.x + f.y * x0.y;
        f = __half22float2(*(__half2*)&a.y); s += f.x * x0.z + f.y * x0.w;
        f = __half22float2(*(__half2*)&a.z); s += f.x * x1.x + f.y * x1.y;
        f = __half22float2(*(__half2*)&a.w); s += f.x * x1.z + f.y * x1.w;
    }
#pragma unroll
    for (int o = 16; o; o >>= 1) s += __shfl_xor_sync(0xffffffffu, s, o);
    if (lane == 0)
        xout[gw] = xin[gw] + g_wdc[gw] * (g_bc[gw] - s);
}

// ---- prolongation / correction: xout = xin + P xc --------------------------
__global__ void k_prolong(const float* __restrict__ xin, float* __restrict__ xout,
                          const float* __restrict__ xc) {
    int t = blockIdx.x * blockDim.x + threadIdx.x;   // t < FN/4
    float4 xi = __ldg((const float4*)xin + t);
#pragma unroll
    for (int k = 0; k < 4; k++) {
        float4 pv = *((const float4*)g_pv[k] + t);
        int4   pc = *((const int4*)g_pc[k] + t);
        xi.x += pv.x * __ldg(&xc[pc.x]);
        xi.y += pv.y * __ldg(&xc[pc.y]);
        xi.z += pv.z * __ldg(&xc[pc.z]);
        xi.w += pv.w * __ldg(&xc[pc.w]);
    }
    ((float4*)xout)[t] = xi;
}

// ---------------------------------------------------------------------------
extern "C" void kernel_launch(void* const* d_in, const int* in_sizes, int n_in,
                              void* d_out, int out_size) {
    const float* b   = (const float*)d_in[0];
    const float* x0  = (const float*)d_in[1];
    const float* Av  = (const float*)d_in[2];
    const float* Pv  = (const float*)d_in[3];
    const int*   Acl = (const int*)d_in[4];
    const int*   Pc  = (const int*)d_in[5];
    float* out = (float*)d_out;

    float *xbuf, *xcbase;
    cudaGetSymbolAddress((void**)&xbuf, g_xbuf);
    cudaGetSymbolAddress((void**)&xcbase, g_xc);
    float* bufs[2] = { xbuf, xbuf + FN };
    float* xc0 = xcbase;
    float* xc1 = xcbase + FNC;

    const int BT = 256;
    const int GB_N4 = (FN / 4 + BT - 1) / BT;        // 256 blocks, 4 rows/thread
    const int GB_NC = (FNC + BT - 1) / BT;           // 16 blocks
    const int GB_CITER = FNC * 32 / BT;              // 512 blocks, warp per row

    // one-time per call: SoA transpose, RAP, fp16 convert (+ re-zero Ac)
    k_prep<<<(FN + BT - 1) / BT, BT>>>(Av, Acl, Pv, Pc);
    k_rap<<<(FN * FD + BT - 1) / BT, BT>>>(Av, Acl, Pv, Pc);
    k_convert<<<FNC * FNC / 8 / BT, BT>>>();

    const float* cur = x0;
    int nb = 0;
    for (int cyc = 0; cyc < 2; ++cyc) {
        for (int s = 0; s < 3; ++s) {
            k_smooth<<<GB_N4, BT>>>(cur, bufs[nb], b);
            cur = bufs[nb]; nb ^= 1;
        }
        k_zero_bc<<<GB_NC, BT>>>();
        k_resid_bc<<<GB_N4, BT>>>(cur, b);
        k_cfirst<<<GB_NC, BT>>>(xc0);
        float* ci = xc0; float* co = xc1;
        for (int t = 0; t < 9; ++t) {
            k_citer<<<GB_CITER, BT>>>(ci, co);
            float* tmp = ci; ci = co; co = tmp;
        }
        k_prolong<<<GB_N4, BT>>>(cur, bufs[nb], ci);
        cur = bufs[nb]; nb ^= 1;
        for (int s = 0; s < 3; ++s) {
            float* dst = (cyc == 1 && s == 2) ? out : bufs[nb];
            k_smooth<<<GB_N4, BT>>>(cur, dst, b);
            cur = dst; nb ^= 1;
        }
    }
}